// round 4
// baseline (speedup 1.0000x reference)
#include <cuda_runtime.h>
#include <cuda_bf16.h>

#define NN 100000
#define EE 3200000
#define DD 16
#define EPSV 1e-5f
#define NB 98              // ceil(NN/1024)
#define DEGB 256
#define PERM_CAP (EE + NN) // padded capacity (<=1 pad record per node)

// ---- static device scratch (allocation-free rule) ----
__device__ int      g_counts[NN];
__device__ int      g_offsets[NN + 1];   // PADDED exclusive offsets (all even)
__device__ int      g_cursor[NN];
__device__ int      g_blocksums[128];
__device__ int      g_deghist[DEGB];
__device__ int      g_degcur[DEGB];
__device__ int4     g_nodeinfo[NN];      // {node, start, end(padded), 0}, degree-sorted
__device__ __align__(16) int2 g_perm[PERM_CAP];  // {src, bitcast(fp32 w)}
__device__ float    g_bufA[NN * DD];
__device__ float    g_bufB[NN * DD];

// ---------------- build ----------------

__global__ void zero_kernel() {
    int i = blockIdx.x * blockDim.x + threadIdx.x;
    if (i < NN) g_counts[i] = 0;
    if (i < DEGB) g_deghist[i] = 0;
}

__global__ void hist_kernel(const int* __restrict__ edge_index) {
    int e = blockIdx.x * blockDim.x + threadIdx.x;
    if (e < EE) atomicAdd(&g_counts[edge_index[EE + e]], 1);
}

// hierarchical scan of PADDED degrees -> g_offsets (exclusive, even)
__global__ void scan1_kernel() {
    __shared__ int sh[1024];
    int b = blockIdx.x, tid = threadIdx.x;
    int i = b * 1024 + tid;
    int v = 0;
    if (i < NN) { int d = g_counts[i]; v = (d + 1) & ~1; }  // pad to even
    sh[tid] = v;
    __syncthreads();
    for (int off = 1; off < 1024; off <<= 1) {
        int t = (tid >= off) ? sh[tid - off] : 0;
        __syncthreads();
        sh[tid] += t;
        __syncthreads();
    }
    if (i < NN) g_offsets[i] = sh[tid] - v;    // block-local exclusive
    if (tid == 1023) g_blocksums[b] = sh[1023];
}

__global__ void scan2_kernel() {
    __shared__ int sh[128];
    int tid = threadIdx.x;
    int v = (tid < NB) ? g_blocksums[tid] : 0;
    sh[tid] = v;
    __syncthreads();
    for (int off = 1; off < 128; off <<= 1) {
        int t = (tid >= off) ? sh[tid - off] : 0;
        __syncthreads();
        sh[tid] += t;
        __syncthreads();
    }
    if (tid < NB) g_blocksums[tid] = sh[tid] - v;  // exclusive block bases
    if (tid == 127) g_offsets[NN] = sh[127];
}

// fixup + cursor init + degree histogram (fused)
__global__ void scan3_kernel() {
    int i = blockIdx.x * blockDim.x + threadIdx.x;
    if (i < NN) {
        int o = g_offsets[i] + g_blocksums[i >> 10];
        g_offsets[i] = o;
        g_cursor[i]  = o;
        int deg = g_counts[i];
        atomicAdd(&g_deghist[deg < DEGB ? deg : DEGB - 1], 1);
    }
}

__global__ void degscan_kernel() {
    __shared__ int sh[DEGB];
    int tid = threadIdx.x;
    int v = g_deghist[tid];
    sh[tid] = v;
    __syncthreads();
    for (int off = 1; off < DEGB; off <<= 1) {
        int t = (tid >= off) ? sh[tid - off] : 0;
        __syncthreads();
        sh[tid] += t;
        __syncthreads();
    }
    g_degcur[tid] = sh[tid] - v;
}

// degree-sorted node records + zero-weight pad fill
__global__ void order_kernel() {
    int i = blockIdx.x * blockDim.x + threadIdx.x;
    if (i < NN) {
        int deg   = g_counts[i];
        int deg_p = (deg + 1) & ~1;
        int bin   = deg < DEGB ? deg : DEGB - 1;
        int pos   = atomicAdd(&g_degcur[bin], 1);
        int start = g_offsets[i];
        g_nodeinfo[pos] = make_int4(i, start, start + deg_p, 0);
        if (deg & 1) {
            // zero-weight self edge: contributes exactly 0 to num and den
            int2 padrec; padrec.x = i; padrec.y = 0;  // 0.0f bits
            g_perm[start + deg] = padrec;
        }
    }
}

__global__ void scatter_kernel(const int* __restrict__ edge_index,
                               const float* __restrict__ edge_attr) {
    int e = blockIdx.x * blockDim.x + threadIdx.x;
    if (e < EE) {
        int s = edge_index[e];
        int d = edge_index[EE + e];
        int pos = atomicAdd(&g_cursor[d], 1);
        int2 rec;
        rec.x = s;
        rec.y = __float_as_int(sqrtf(edge_attr[e]));   // exact fp32 weight
        g_perm[pos] = rec;
    }
}

// ---------------- iteration ----------------
// 4 lanes per node; lane l owns dims [4l, 4l+4).  256 thr = 64 nodes/block.
// Edge lists are even-length and 16B-aligned -> consume 2 records per trip.
__global__ __launch_bounds__(256) void iterate_kernel(
        const float4* __restrict__ sin,
        const float4* __restrict__ x0v,
        float4* __restrict__ sout) {
    int idx  = blockIdx.x * 64 + (threadIdx.x >> 2);
    int lane = threadIdx.x & 3;
    if (idx >= NN) return;

    int4 info = g_nodeinfo[idx];
    int node  = info.x;
    float4 xi = sin[node * 4 + lane];

    float4 num = make_float4(0.f, 0.f, 0.f, 0.f);
    float4 den = make_float4(0.f, 0.f, 0.f, 0.f);

    const int4* pp = (const int4*)(g_perm + info.y);
    int pairs = (info.z - info.y) >> 1;

    for (int t = 0; t < pairs; ++t) {
        int4 rr = pp[t];                       // two edge records, 16B aligned
        float we0 = __int_as_float(rr.y);
        float we1 = __int_as_float(rr.w);
        float4 xj0 = sin[rr.x * 4 + lane];     // two independent gathers
        float4 xj1 = sin[rr.z * 4 + lane];

        float a0 = __fdividef(we0, fabsf(xj0.x - xi.x + EPSV));
        float a1 = __fdividef(we0, fabsf(xj0.y - xi.y + EPSV));
        float a2 = __fdividef(we0, fabsf(xj0.z - xi.z + EPSV));
        float a3 = __fdividef(we0, fabsf(xj0.w - xi.w + EPSV));
        float b0 = __fdividef(we1, fabsf(xj1.x - xi.x + EPSV));
        float b1 = __fdividef(we1, fabsf(xj1.y - xi.y + EPSV));
        float b2 = __fdividef(we1, fabsf(xj1.z - xi.z + EPSV));
        float b3 = __fdividef(we1, fabsf(xj1.w - xi.w + EPSV));

        num.x += a0 * xj0.x;  den.x += a0;
        num.y += a1 * xj0.y;  den.y += a1;
        num.z += a2 * xj0.z;  den.z += a2;
        num.w += a3 * xj0.w;  den.w += a3;
        num.x += b0 * xj1.x;  den.x += b0;
        num.y += b1 * xj1.y;  den.y += b1;
        num.z += b2 * xj1.z;  den.z += b2;
        num.w += b3 * xj1.w;  den.w += b3;
    }

    float4 x0n = x0v[node * 4 + lane];
    float4 r;
    r.x = __fdividef(x0n.x + num.x, 1.0f + den.x);
    r.y = __fdividef(x0n.y + num.y, 1.0f + den.y);
    r.z = __fdividef(x0n.z + num.z, 1.0f + den.z);
    r.w = __fdividef(x0n.w + num.w, 1.0f + den.w);
    sout[node * 4 + lane] = r;
}

// ---------------- launch ----------------

extern "C" void kernel_launch(void* const* d_in, const int* in_sizes, int n_in,
                              void* d_out, int out_size) {
    const float* signal     = (const float*)d_in[0];
    const float* x0         = (const float*)d_in[1];
    const float* edge_attr  = (const float*)d_in[2];
    const int*   edge_index = (const int*)  d_in[3];
    float* out = (float*)d_out;

    float *bufA, *bufB;
    cudaGetSymbolAddress((void**)&bufA, g_bufA);
    cudaGetSymbolAddress((void**)&bufB, g_bufB);

    // CSR build + degree-balanced ordering (once per launch)
    zero_kernel<<<(NN + 255) / 256, 256>>>();
    hist_kernel<<<(EE + 255) / 256, 256>>>(edge_index);
    scan1_kernel<<<NB, 1024>>>();
    scan2_kernel<<<1, 128>>>();
    scan3_kernel<<<(NN + 255) / 256, 256>>>();
    degscan_kernel<<<1, DEGB>>>();
    order_kernel<<<(NN + 255) / 256, 256>>>();
    scatter_kernel<<<(EE + 255) / 256, 256>>>(edge_index, edge_attr);

    int grid = (NN + 63) / 64;
    const float4* x0v = (const float4*)x0;

    // itr = 5: signal -> A -> B -> A -> B -> out
    iterate_kernel<<<grid, 256>>>((const float4*)signal, x0v, (float4*)bufA);
    iterate_kernel<<<grid, 256>>>((const float4*)bufA,   x0v, (float4*)bufB);
    iterate_kernel<<<grid, 256>>>((const float4*)bufB,   x0v, (float4*)bufA);
    iterate_kernel<<<grid, 256>>>((const float4*)bufA,   x0v, (float4*)bufB);
    iterate_kernel<<<grid, 256>>>((const float4*)bufB,   x0v, (float4*)out);
}

// round 5
// speedup vs baseline: 1.2481x; 1.2481x over previous
#include <cuda_runtime.h>
#include <cuda_bf16.h>

#define NN 100000
#define EE 3200000
#define DD 16
#define EPSV 1e-5f
#define NB 98              // ceil(NN/1024)
#define DEGB 256

// ---- static device scratch (allocation-free rule) ----
__device__ int      g_counts[NN];
__device__ int      g_offsets[NN + 1];
__device__ int      g_cursor[NN];
__device__ int      g_blocksums[128];
__device__ int      g_deghist[DEGB];
__device__ int      g_degcur[DEGB];
__device__ int4     g_nodeinfo[NN];     // {node, start, end, pad}, degree-sorted
__device__ int2     g_perm[EE];         // {src, bitcast(sqrt(edge_attr))} — exact
__device__ float    g_bufA[NN * DD];
__device__ float    g_bufB[NN * DD];

// ---------------- build ----------------

__global__ void zero_kernel() {
    int i = blockIdx.x * blockDim.x + threadIdx.x;
    if (i < NN) g_counts[i] = 0;
    if (i < DEGB) g_deghist[i] = 0;
}

// 4 edges per thread via int4
__global__ void hist_kernel(const int4* __restrict__ dst4) {
    int i = blockIdx.x * blockDim.x + threadIdx.x;
    if (i < EE / 4) {
        int4 d = dst4[i];
        atomicAdd(&g_counts[d.x], 1);
        atomicAdd(&g_counts[d.y], 1);
        atomicAdd(&g_counts[d.z], 1);
        atomicAdd(&g_counts[d.w], 1);
    }
}

// hierarchical scan of g_counts -> g_offsets (exclusive)
__global__ void scan1_kernel() {
    __shared__ int sh[1024];
    int b = blockIdx.x, tid = threadIdx.x;
    int i = b * 1024 + tid;
    int v = (i < NN) ? g_counts[i] : 0;
    sh[tid] = v;
    __syncthreads();
    for (int off = 1; off < 1024; off <<= 1) {
        int t = (tid >= off) ? sh[tid - off] : 0;
        __syncthreads();
        sh[tid] += t;
        __syncthreads();
    }
    if (i < NN) g_offsets[i] = sh[tid] - v;    // block-local exclusive
    if (tid == 1023) g_blocksums[b] = sh[1023];
}

__global__ void scan2_kernel() {
    __shared__ int sh[128];
    int tid = threadIdx.x;
    int v = (tid < NB) ? g_blocksums[tid] : 0;
    sh[tid] = v;
    __syncthreads();
    for (int off = 1; off < 128; off <<= 1) {
        int t = (tid >= off) ? sh[tid - off] : 0;
        __syncthreads();
        sh[tid] += t;
        __syncthreads();
    }
    if (tid < NB) g_blocksums[tid] = sh[tid] - v;  // exclusive block bases
    if (tid == 127) g_offsets[NN] = sh[127];       // grand total (== EE)
}

// fixup + cursor init + degree histogram (fused)
__global__ void scan3_kernel() {
    int i = blockIdx.x * blockDim.x + threadIdx.x;
    if (i < NN) {
        int o = g_offsets[i] + g_blocksums[i >> 10];
        g_offsets[i] = o;
        g_cursor[i]  = o;
        int deg = g_counts[i];
        atomicAdd(&g_deghist[deg < DEGB ? deg : DEGB - 1], 1);
    }
}

__global__ void degscan_kernel() {
    __shared__ int sh[DEGB];
    int tid = threadIdx.x;
    int v = g_deghist[tid];
    sh[tid] = v;
    __syncthreads();
    for (int off = 1; off < DEGB; off <<= 1) {
        int t = (tid >= off) ? sh[tid - off] : 0;
        __syncthreads();
        sh[tid] += t;
        __syncthreads();
    }
    g_degcur[tid] = sh[tid] - v;
}

// degree-sorted node records so each warp gets 8 equal-degree nodes
__global__ void order_kernel() {
    int i = blockIdx.x * blockDim.x + threadIdx.x;
    if (i < NN) {
        int deg = g_counts[i];
        int bin = deg < DEGB ? deg : DEGB - 1;
        int pos = atomicAdd(&g_degcur[bin], 1);
        int start = g_offsets[i];
        g_nodeinfo[pos] = make_int4(i, start, start + deg, 0);
    }
}

__global__ void scatter_kernel(const int* __restrict__ edge_index,
                               const float* __restrict__ edge_attr) {
    int e = blockIdx.x * blockDim.x + threadIdx.x;
    if (e < EE) {
        int s = edge_index[e];
        int d = edge_index[EE + e];
        int pos = atomicAdd(&g_cursor[d], 1);
        int2 rec;
        rec.x = s;
        rec.y = __float_as_int(sqrtf(edge_attr[e]));   // exact fp32 weight
        g_perm[pos] = rec;
    }
}

// ---------------- iteration ----------------
// 4 lanes per node; lane l owns dims [4l, 4l+4).  256 thr = 64 nodes/block.
__global__ __launch_bounds__(256) void iterate_kernel(
        const float4* __restrict__ sin,
        const float4* __restrict__ x0v,
        float4* __restrict__ sout) {
    int idx  = blockIdx.x * 64 + (threadIdx.x >> 2);
    int lane = threadIdx.x & 3;
    if (idx >= NN) return;

    int4 info = g_nodeinfo[idx];
    int node  = info.x;
    float4 xi = sin[node * 4 + lane];

    float4 num = make_float4(0.f, 0.f, 0.f, 0.f);
    float4 den = make_float4(0.f, 0.f, 0.f, 0.f);

    #pragma unroll 4
    for (int e = info.y; e < info.z; ++e) {
        int2 rec  = g_perm[e];                 // broadcast across the 4 lanes
        float we  = __int_as_float(rec.y);
        float4 xj = sin[rec.x * 4 + lane];     // coalesced 64B gather per group

        float w0 = __fdividef(we, fabsf(xj.x - xi.x + EPSV));
        float w1 = __fdividef(we, fabsf(xj.y - xi.y + EPSV));
        float w2 = __fdividef(we, fabsf(xj.z - xi.z + EPSV));
        float w3 = __fdividef(we, fabsf(xj.w - xi.w + EPSV));
        num.x += w0 * xj.x;  den.x += w0;
        num.y += w1 * xj.y;  den.y += w1;
        num.z += w2 * xj.z;  den.z += w2;
        num.w += w3 * xj.w;  den.w += w3;
    }

    float4 x0n = x0v[node * 4 + lane];
    float4 r;
    r.x = __fdividef(x0n.x + num.x, 1.0f + den.x);
    r.y = __fdividef(x0n.y + num.y, 1.0f + den.y);
    r.z = __fdividef(x0n.z + num.z, 1.0f + den.z);
    r.w = __fdividef(x0n.w + num.w, 1.0f + den.w);
    sout[node * 4 + lane] = r;
}

// ---------------- launch ----------------

extern "C" void kernel_launch(void* const* d_in, const int* in_sizes, int n_in,
                              void* d_out, int out_size) {
    const float* signal     = (const float*)d_in[0];
    const float* x0         = (const float*)d_in[1];
    const float* edge_attr  = (const float*)d_in[2];
    const int*   edge_index = (const int*)  d_in[3];
    float* out = (float*)d_out;

    float *bufA, *bufB;
    cudaGetSymbolAddress((void**)&bufA, g_bufA);
    cudaGetSymbolAddress((void**)&bufB, g_bufB);

    // CSR build + degree-balanced ordering (once per launch)
    zero_kernel<<<(NN + 255) / 256, 256>>>();
    hist_kernel<<<(EE / 4 + 255) / 256, 256>>>((const int4*)(edge_index + EE));
    scan1_kernel<<<NB, 1024>>>();
    scan2_kernel<<<1, 128>>>();
    scan3_kernel<<<(NN + 255) / 256, 256>>>();
    degscan_kernel<<<1, DEGB>>>();
    order_kernel<<<(NN + 255) / 256, 256>>>();
    scatter_kernel<<<(EE + 255) / 256, 256>>>(edge_index, edge_attr);

    int grid = (NN + 63) / 64;
    const float4* x0v = (const float4*)x0;

    // itr = 5: signal -> A -> B -> A -> B -> out
    iterate_kernel<<<grid, 256>>>((const float4*)signal, x0v, (float4*)bufA);
    iterate_kernel<<<grid, 256>>>((const float4*)bufA,   x0v, (float4*)bufB);
    iterate_kernel<<<grid, 256>>>((const float4*)bufB,   x0v, (float4*)bufA);
    iterate_kernel<<<grid, 256>>>((const float4*)bufA,   x0v, (float4*)bufB);
    iterate_kernel<<<grid, 256>>>((const float4*)bufB,   x0v, (float4*)out);
}

// round 6
// speedup vs baseline: 1.4160x; 1.1346x over previous
#include <cuda_runtime.h>
#include <cuda_bf16.h>

#define NN 100000
#define EE 3200000
#define DD 16
#define EPSV 1e-5f
#define NB 98              // ceil(NN/1024)
#define DEGB 256

// ---- static device scratch (allocation-free rule) ----
__device__ int      g_counts[NN];
__device__ int      g_offsets[NN + 1];
__device__ int      g_cursor[NN];
__device__ int      g_blocksums[128];
__device__ int      g_deghist[DEGB];
__device__ int      g_degcur[DEGB];
__device__ int4     g_nodeinfo[NN];     // {node, start, end, pad}, degree-sorted
__device__ int2     g_perm[EE];         // {src, bitcast(sqrt(edge_attr))} — exact
__device__ float    g_bufA[NN * DD];
__device__ float    g_bufB[NN * DD];

// ---------------- build ----------------

__global__ void zero_kernel() {
    int i = blockIdx.x * blockDim.x + threadIdx.x;
    if (i < NN) g_counts[i] = 0;
    if (i < DEGB) g_deghist[i] = 0;
}

// 4 edges per thread via int4 (EE divisible by 4)
__global__ void hist_kernel(const int4* __restrict__ dst4) {
    int i = blockIdx.x * blockDim.x + threadIdx.x;
    if (i < EE / 4) {
        int4 d = dst4[i];
        atomicAdd(&g_counts[d.x], 1);
        atomicAdd(&g_counts[d.y], 1);
        atomicAdd(&g_counts[d.z], 1);
        atomicAdd(&g_counts[d.w], 1);
    }
}

// hierarchical scan of g_counts -> g_offsets (exclusive)
__global__ void scan1_kernel() {
    __shared__ int sh[1024];
    int b = blockIdx.x, tid = threadIdx.x;
    int i = b * 1024 + tid;
    int v = (i < NN) ? g_counts[i] : 0;
    sh[tid] = v;
    __syncthreads();
    for (int off = 1; off < 1024; off <<= 1) {
        int t = (tid >= off) ? sh[tid - off] : 0;
        __syncthreads();
        sh[tid] += t;
        __syncthreads();
    }
    if (i < NN) g_offsets[i] = sh[tid] - v;    // block-local exclusive
    if (tid == 1023) g_blocksums[b] = sh[1023];
}

__global__ void scan2_kernel() {
    __shared__ int sh[128];
    int tid = threadIdx.x;
    int v = (tid < NB) ? g_blocksums[tid] : 0;
    sh[tid] = v;
    __syncthreads();
    for (int off = 1; off < 128; off <<= 1) {
        int t = (tid >= off) ? sh[tid - off] : 0;
        __syncthreads();
        sh[tid] += t;
        __syncthreads();
    }
    if (tid < NB) g_blocksums[tid] = sh[tid] - v;  // exclusive block bases
    if (tid == 127) g_offsets[NN] = sh[127];       // grand total (== EE)
}

// fixup + cursor init + degree histogram (fused)
__global__ void scan3_kernel() {
    int i = blockIdx.x * blockDim.x + threadIdx.x;
    if (i < NN) {
        int o = g_offsets[i] + g_blocksums[i >> 10];
        g_offsets[i] = o;
        g_cursor[i]  = o;
        int deg = g_counts[i];
        atomicAdd(&g_deghist[deg < DEGB ? deg : DEGB - 1], 1);
    }
}

__global__ void degscan_kernel() {
    __shared__ int sh[DEGB];
    int tid = threadIdx.x;
    int v = g_deghist[tid];
    sh[tid] = v;
    __syncthreads();
    for (int off = 1; off < DEGB; off <<= 1) {
        int t = (tid >= off) ? sh[tid - off] : 0;
        __syncthreads();
        sh[tid] += t;
        __syncthreads();
    }
    g_degcur[tid] = sh[tid] - v;
}

// degree-sorted node records so each warp gets 8 equal-degree nodes
__global__ void order_kernel() {
    int i = blockIdx.x * blockDim.x + threadIdx.x;
    if (i < NN) {
        int deg = g_counts[i];
        int bin = deg < DEGB ? deg : DEGB - 1;
        int pos = atomicAdd(&g_degcur[bin], 1);
        int start = g_offsets[i];
        g_nodeinfo[pos] = make_int4(i, start, start + deg, 0);
    }
}

__global__ void scatter_kernel(const int* __restrict__ edge_index,
                               const float* __restrict__ edge_attr) {
    int e = blockIdx.x * blockDim.x + threadIdx.x;
    if (e < EE) {
        int s = edge_index[e];
        int d = edge_index[EE + e];
        int pos = atomicAdd(&g_cursor[d], 1);
        int2 rec;
        rec.x = s;
        rec.y = __float_as_int(sqrtf(edge_attr[e]));   // exact fp32 weight
        g_perm[pos] = rec;
    }
}

// ---------------- iteration ----------------
// 4 lanes per node; lane l owns dims [4l, 4l+4).  256 thr = 64 nodes/block.
__global__ __launch_bounds__(256) void iterate_kernel(
        const float4* __restrict__ sin,
        const float4* __restrict__ x0v,
        float4* __restrict__ sout) {
    int idx  = blockIdx.x * 64 + (threadIdx.x >> 2);
    int lane = threadIdx.x & 3;
    if (idx >= NN) return;

    int4 info = g_nodeinfo[idx];
    int node  = info.x;
    float4 xi = sin[node * 4 + lane];

    float4 num = make_float4(0.f, 0.f, 0.f, 0.f);
    float4 den = make_float4(0.f, 0.f, 0.f, 0.f);

    #pragma unroll 2
    for (int e = info.y; e < info.z; ++e) {
        int2 rec  = g_perm[e];                 // broadcast across the 4 lanes
        float we  = __int_as_float(rec.y);
        float4 xj = sin[rec.x * 4 + lane];     // coalesced 64B gather per group

        float w0 = __fdividef(we, fabsf(xj.x - xi.x + EPSV));
        float w1 = __fdividef(we, fabsf(xj.y - xi.y + EPSV));
        float w2 = __fdividef(we, fabsf(xj.z - xi.z + EPSV));
        float w3 = __fdividef(we, fabsf(xj.w - xi.w + EPSV));
        num.x += w0 * xj.x;  den.x += w0;
        num.y += w1 * xj.y;  den.y += w1;
        num.z += w2 * xj.z;  den.z += w2;
        num.w += w3 * xj.w;  den.w += w3;
    }

    float4 x0n = x0v[node * 4 + lane];
    float4 r;
    r.x = __fdividef(x0n.x + num.x, 1.0f + den.x);
    r.y = __fdividef(x0n.y + num.y, 1.0f + den.y);
    r.z = __fdividef(x0n.z + num.z, 1.0f + den.z);
    r.w = __fdividef(x0n.w + num.w, 1.0f + den.w);
    sout[node * 4 + lane] = r;
}

// ---------------- launch ----------------

extern "C" void kernel_launch(void* const* d_in, const int* in_sizes, int n_in,
                              void* d_out, int out_size) {
    const float* signal     = (const float*)d_in[0];
    const float* x0         = (const float*)d_in[1];
    const float* edge_attr  = (const float*)d_in[2];
    const int*   edge_index = (const int*)  d_in[3];
    float* out = (float*)d_out;

    float *bufA, *bufB;
    cudaGetSymbolAddress((void**)&bufA, g_bufA);
    cudaGetSymbolAddress((void**)&bufB, g_bufB);

    // CSR build + degree-balanced ordering (once per launch)
    zero_kernel<<<(NN + 255) / 256, 256>>>();
    hist_kernel<<<(EE / 4 + 255) / 256, 256>>>((const int4*)(edge_index + EE));
    scan1_kernel<<<NB, 1024>>>();
    scan2_kernel<<<1, 128>>>();
    scan3_kernel<<<(NN + 255) / 256, 256>>>();
    degscan_kernel<<<1, DEGB>>>();
    order_kernel<<<(NN + 255) / 256, 256>>>();
    scatter_kernel<<<(EE + 255) / 256, 256>>>(edge_index, edge_attr);

    int grid = (NN + 63) / 64;
    const float4* x0v = (const float4*)x0;

    // itr = 5: signal -> A -> B -> A -> B -> out
    iterate_kernel<<<grid, 256>>>((const float4*)signal, x0v, (float4*)bufA);
    iterate_kernel<<<grid, 256>>>((const float4*)bufA,   x0v, (float4*)bufB);
    iterate_kernel<<<grid, 256>>>((const float4*)bufB,   x0v, (float4*)bufA);
    iterate_kernel<<<grid, 256>>>((const float4*)bufA,   x0v, (float4*)bufB);
    iterate_kernel<<<grid, 256>>>((const float4*)bufB,   x0v, (float4*)out);
}

// round 7
// speedup vs baseline: 1.4285x; 1.0088x over previous
#include <cuda_runtime.h>
#include <cuda_bf16.h>

#define NN 100000
#define EE 3200000
#define DD 16
#define EPSV 1e-5f
#define NB 98              // ceil(NN/1024)
#define DEGB 256

// ---- static device scratch (allocation-free rule) ----
__device__ int      g_counts[NN];
__device__ int      g_offsets[NN + 1];
__device__ int      g_cursor[NN];
__device__ int      g_blocksums[128];
__device__ int      g_deghist[DEGB];
__device__ int      g_degcur[DEGB];
__device__ int4     g_nodeinfo[NN];     // {node, start, end, pad}, degree-sorted
__device__ int2     g_perm[EE];         // {src, bitcast(sqrt(edge_attr))} — exact
__device__ float    g_bufA[NN * DD];
__device__ float    g_bufB[NN * DD];

// ---------------- build ----------------

__global__ void zero_kernel() {
    int i = blockIdx.x * blockDim.x + threadIdx.x;
    if (i < NN) g_counts[i] = 0;
    if (i < DEGB) g_deghist[i] = 0;
}

// 4 edges per thread via int4 (EE divisible by 4)
__global__ void hist_kernel(const int4* __restrict__ dst4) {
    int i = blockIdx.x * blockDim.x + threadIdx.x;
    if (i < EE / 4) {
        int4 d = dst4[i];
        atomicAdd(&g_counts[d.x], 1);
        atomicAdd(&g_counts[d.y], 1);
        atomicAdd(&g_counts[d.z], 1);
        atomicAdd(&g_counts[d.w], 1);
    }
}

// hierarchical scan of g_counts -> g_offsets (exclusive)
__global__ void scan1_kernel() {
    __shared__ int sh[1024];
    int b = blockIdx.x, tid = threadIdx.x;
    int i = b * 1024 + tid;
    int v = (i < NN) ? g_counts[i] : 0;
    sh[tid] = v;
    __syncthreads();
    for (int off = 1; off < 1024; off <<= 1) {
        int t = (tid >= off) ? sh[tid - off] : 0;
        __syncthreads();
        sh[tid] += t;
        __syncthreads();
    }
    if (i < NN) g_offsets[i] = sh[tid] - v;    // block-local exclusive
    if (tid == 1023) g_blocksums[b] = sh[1023];
}

__global__ void scan2_kernel() {
    __shared__ int sh[128];
    int tid = threadIdx.x;
    int v = (tid < NB) ? g_blocksums[tid] : 0;
    sh[tid] = v;
    __syncthreads();
    for (int off = 1; off < 128; off <<= 1) {
        int t = (tid >= off) ? sh[tid - off] : 0;
        __syncthreads();
        sh[tid] += t;
        __syncthreads();
    }
    if (tid < NB) g_blocksums[tid] = sh[tid] - v;  // exclusive block bases
    if (tid == 127) g_offsets[NN] = sh[127];       // grand total (== EE)
}

// fixup + cursor init + degree histogram (fused)
__global__ void scan3_kernel() {
    int i = blockIdx.x * blockDim.x + threadIdx.x;
    if (i < NN) {
        int o = g_offsets[i] + g_blocksums[i >> 10];
        g_offsets[i] = o;
        g_cursor[i]  = o;
        int deg = g_counts[i];
        atomicAdd(&g_deghist[deg < DEGB ? deg : DEGB - 1], 1);
    }
}

__global__ void degscan_kernel() {
    __shared__ int sh[DEGB];
    int tid = threadIdx.x;
    int v = g_deghist[tid];
    sh[tid] = v;
    __syncthreads();
    for (int off = 1; off < DEGB; off <<= 1) {
        int t = (tid >= off) ? sh[tid - off] : 0;
        __syncthreads();
        sh[tid] += t;
        __syncthreads();
    }
    g_degcur[tid] = sh[tid] - v;
}

// degree-sorted node records so each warp gets 8 equal-degree nodes
__global__ void order_kernel() {
    int i = blockIdx.x * blockDim.x + threadIdx.x;
    if (i < NN) {
        int deg = g_counts[i];
        int bin = deg < DEGB ? deg : DEGB - 1;
        int pos = atomicAdd(&g_degcur[bin], 1);
        int start = g_offsets[i];
        g_nodeinfo[pos] = make_int4(i, start, start + deg, 0);
    }
}

// 4 edges per thread: int4 src, int4 dst, float4 attr -> 4 independent
// atomic+store chains in flight (scatter was latency-bound at 1/thread)
__global__ void scatter_kernel(const int4* __restrict__ src4,
                               const int4* __restrict__ dst4,
                               const float4* __restrict__ attr4) {
    int i = blockIdx.x * blockDim.x + threadIdx.x;
    if (i < EE / 4) {
        int4   s = src4[i];
        int4   d = dst4[i];
        float4 a = attr4[i];
        int p0 = atomicAdd(&g_cursor[d.x], 1);
        int p1 = atomicAdd(&g_cursor[d.y], 1);
        int p2 = atomicAdd(&g_cursor[d.z], 1);
        int p3 = atomicAdd(&g_cursor[d.w], 1);
        int2 r0; r0.x = s.x; r0.y = __float_as_int(sqrtf(a.x));
        int2 r1; r1.x = s.y; r1.y = __float_as_int(sqrtf(a.y));
        int2 r2; r2.x = s.z; r2.y = __float_as_int(sqrtf(a.z));
        int2 r3; r3.x = s.w; r3.y = __float_as_int(sqrtf(a.w));
        g_perm[p0] = r0;
        g_perm[p1] = r1;
        g_perm[p2] = r2;
        g_perm[p3] = r3;
    }
}

// ---------------- iteration ----------------
// 4 lanes per node; lane l owns dims [4l, 4l+4).  256 thr = 64 nodes/block.
__global__ __launch_bounds__(256) void iterate_kernel(
        const float4* __restrict__ sin,
        const float4* __restrict__ x0v,
        float4* __restrict__ sout) {
    int idx  = blockIdx.x * 64 + (threadIdx.x >> 2);
    int lane = threadIdx.x & 3;
    if (idx >= NN) return;

    int4 info = g_nodeinfo[idx];
    int node  = info.x;
    float4 xi = sin[node * 4 + lane];

    float4 num = make_float4(0.f, 0.f, 0.f, 0.f);
    float4 den = make_float4(0.f, 0.f, 0.f, 0.f);

    #pragma unroll 2
    for (int e = info.y; e < info.z; ++e) {
        int2 rec  = g_perm[e];                 // broadcast across the 4 lanes
        float we  = __int_as_float(rec.y);
        float4 xj = sin[rec.x * 4 + lane];     // coalesced 64B gather per group

        float w0 = __fdividef(we, fabsf(xj.x - xi.x + EPSV));
        float w1 = __fdividef(we, fabsf(xj.y - xi.y + EPSV));
        float w2 = __fdividef(we, fabsf(xj.z - xi.z + EPSV));
        float w3 = __fdividef(we, fabsf(xj.w - xi.w + EPSV));
        num.x += w0 * xj.x;  den.x += w0;
        num.y += w1 * xj.y;  den.y += w1;
        num.z += w2 * xj.z;  den.z += w2;
        num.w += w3 * xj.w;  den.w += w3;
    }

    float4 x0n = x0v[node * 4 + lane];
    float4 r;
    r.x = __fdividef(x0n.x + num.x, 1.0f + den.x);
    r.y = __fdividef(x0n.y + num.y, 1.0f + den.y);
    r.z = __fdividef(x0n.z + num.z, 1.0f + den.z);
    r.w = __fdividef(x0n.w + num.w, 1.0f + den.w);
    sout[node * 4 + lane] = r;
}

// ---------------- launch ----------------

extern "C" void kernel_launch(void* const* d_in, const int* in_sizes, int n_in,
                              void* d_out, int out_size) {
    const float* signal     = (const float*)d_in[0];
    const float* x0         = (const float*)d_in[1];
    const float* edge_attr  = (const float*)d_in[2];
    const int*   edge_index = (const int*)  d_in[3];
    float* out = (float*)d_out;

    float *bufA, *bufB;
    cudaGetSymbolAddress((void**)&bufA, g_bufA);
    cudaGetSymbolAddress((void**)&bufB, g_bufB);

    // CSR build + degree-balanced ordering (once per launch)
    zero_kernel<<<(NN + 255) / 256, 256>>>();
    hist_kernel<<<(EE / 4 + 255) / 256, 256>>>((const int4*)(edge_index + EE));
    scan1_kernel<<<NB, 1024>>>();
    scan2_kernel<<<1, 128>>>();
    scan3_kernel<<<(NN + 255) / 256, 256>>>();
    degscan_kernel<<<1, DEGB>>>();
    order_kernel<<<(NN + 255) / 256, 256>>>();
    scatter_kernel<<<(EE / 4 + 255) / 256, 256>>>(
        (const int4*)edge_index,
        (const int4*)(edge_index + EE),
        (const float4*)edge_attr);

    int grid = (NN + 63) / 64;
    const float4* x0v = (const float4*)x0;

    // itr = 5: signal -> A -> B -> A -> B -> out
    iterate_kernel<<<grid, 256>>>((const float4*)signal, x0v, (float4*)bufA);
    iterate_kernel<<<grid, 256>>>((const float4*)bufA,   x0v, (float4*)bufB);
    iterate_kernel<<<grid, 256>>>((const float4*)bufB,   x0v, (float4*)bufA);
    iterate_kernel<<<grid, 256>>>((const float4*)bufA,   x0v, (float4*)bufB);
    iterate_kernel<<<grid, 256>>>((const float4*)bufB,   x0v, (float4*)out);
}